// round 12
// baseline (speedup 1.0000x reference)
#include <cuda_runtime.h>
#include <cuda_bf16.h>
#include <math.h>

// AssociativeLIF forward: T=8, B=128, D=8192, NC=64
// d_out = [ ss (T,B,D) | vt (T,B,D) ] float32
// Cluster of 2 CTAs per batch row; CTA h owns d in [h*4096, (h+1)*4096).
// Thread owns d = h*4096 + 4*tid + j and d = h*4096 + 2048 + 4*tid + j, j=0..3.
// Fast path (cids[d] == d%64): all 8 neurons of a thread hit clusters 4*(tid&15)+j.

#define T_STEPS 8
#define BATCH   128
#define DIM     8192
#define NC      64
#define TPB     512
#define HALF    4096
#define V_RESET (-0.1f)

__device__ __forceinline__ unsigned smem_u32(const void* p) {
    return (unsigned)__cvta_generic_to_shared(p);
}
__device__ __forceinline__ unsigned mapa_u32(unsigned addr, unsigned rank) {
    unsigned r;
    asm("mapa.shared::cluster.u32 %0, %1, %2;" : "=r"(r) : "r"(addr), "r"(rank));
    return r;
}
__device__ __forceinline__ void st_cluster_u32(unsigned addr, unsigned v) {
    asm volatile("st.shared::cluster.u32 [%0], %1;" :: "r"(addr), "r"(v) : "memory");
}
__device__ __forceinline__ void cluster_sync() {
    asm volatile("barrier.cluster.arrive.aligned;" ::: "memory");
    asm volatile("barrier.cluster.wait.aligned;"   ::: "memory");
}

__global__ __launch_bounds__(TPB, 2) __cluster_dims__(2, 1, 1)
void assoc_lif_kernel(const float* __restrict__ x,        // [T,B,D]
                      const float* __restrict__ th_raw,   // [D]
                      const float* __restrict__ bm_raw,   // [1]
                      const float* __restrict__ bs_raw,   // [1]
                      const float* __restrict__ nw,       // [NC,NC]
                      const float* __restrict__ gain,     // [NC]
                      const int*   __restrict__ cids,     // [D]
                      float* __restrict__ out_s,          // [T,B,D]
                      float* __restrict__ out_v)          // [T,B,D]
{
    __shared__ float Wts[NC * NC];          // Wts[j*64+c] = sigmoid(nw[c][j]) / 128 (exact scale)
    __shared__ float g_sm[NC];
    __shared__ unsigned cnt[2][16];         // local packed byte counts, double-buffered
    __shared__ unsigned rcnt[2][16];        // partner-written packed counts
    __shared__ float cf_slow[2][NC];        // fallback local float counts
    __shared__ float rslow[2][NC];          // fallback partner counts
    __shared__ float partial[8][NC];        // distributed-dot partials
    __shared__ __align__(16) float ns[NC];
    __shared__ float bm_sh, bs_sh;

    const int bid = blockIdx.x;
    const int b   = bid >> 1;
    const int h   = bid & 1;                // half of D owned by this CTA
    const unsigned prank = (unsigned)(h ^ 1);
    const int tid = threadIdx.x;

    // ---- one-time parameter prep ----
    for (int idx = tid; idx < NC * NC; idx += TPB) {
        int c = idx >> 6, j = idx & 63;                     // nw row-major [c][j]
        Wts[j * NC + c] = (1.0f / (1.0f + expf(-nw[idx]))) * (1.0f / 128.0f);
    }
    if (tid < NC)      g_sm[tid] = gain[tid];
    if (tid < 32)      ((unsigned*)cnt)[tid] = 0u;
    if (tid < 2 * NC)  ((float*)cf_slow)[tid] = 0.0f;
    if (tid == 0) {
        float bm = 1.0f / (1.0f + expf(-bm_raw[0]));
        bm_sh = fminf(fmaxf(bm, 0.8f), 0.98f);
        bs_sh = 1.0f / (1.0f + expf(-bs_raw[0]));
    }

    // fast path iff cids[d] == d % 64 over the WHOLE row (both CTAs agree by construction)
    bool okf = true;
    #pragma unroll
    for (int q = 0; q < 4; q++) {           // offsets 0,2048,4096,6144 cover both halves
        #pragma unroll
        for (int j = 0; j < 4; j++) {
            int d = q * 2048 + 4 * tid + j;
            okf &= (cids[d] == (d & 63));
        }
    }
    const bool fast = (__syncthreads_and((int)okf) != 0);   // also fences smem init

    const float bm = bm_sh, bs = bs_sh, om = 1.0f - bm;

    const size_t bd4   = ((size_t)b * DIM + (size_t)h * HALF) / 4;
    const size_t step4 = (size_t)BATCH * DIM / 4;

    const float4* x4 = (const float4*)x     + bd4 + tid;
    float4*       s4 = (float4*)out_s       + bd4 + tid;
    float4*       v4 = (float4*)out_v       + bd4 + tid;

    // ---- per-thread state ----
    float v[8], isyn[8], th[8], xv[8];
    unsigned s1 = 0, s2 = 0;            // spike masks at t-1, t-2 (refractory)
    {
        const float4* t4 = (const float4*)th_raw + (size_t)h * (HALF / 4) + tid;
        float4 t0 = t4[0], t1 = t4[512];
        th[0]=t0.x; th[1]=t0.y; th[2]=t0.z; th[3]=t0.w;
        th[4]=t1.x; th[5]=t1.y; th[6]=t1.z; th[7]=t1.w;
        #pragma unroll
        for (int k = 0; k < 8; k++) {
            th[k] = fminf(fmaxf(th[k], 0.05f), 0.5f);
            v[k] = 0.0f; isyn[k] = 0.0f;
        }
        float4 a = x4[0], c = x4[512];      // preload t=0
        xv[0]=a.x; xv[1]=a.y; xv[2]=a.z; xv[3]=a.w;
        xv[4]=c.x; xv[5]=c.y; xv[6]=c.z; xv[7]=c.w;
    }

    for (int t = 0; t < T_STEPS; t++) {
        const int buf = t & 1;
        const bool need_cascade = (t + 1 < T_STEPS);   // i_syn dead after last step

        // ---- LIF update + spike (refrac>0 <=> spiked at t-1 or t-2) ----
        const unsigned refr = s1 | s2;
        unsigned smask = 0;
        #pragma unroll
        for (int k = 0; k < 8; k++) {
            isyn[k] = fmaf(bs, isyn[k], xv[k]);
            float nv = fmaf(bm, v[k], om * isyn[k]);
            v[k] = ((refr >> k) & 1u) ? V_RESET : nv;
            if (v[k] >= th[k]) smask |= (1u << k);
        }
        s2 = s1; s1 = smask;

        // ---- local spike counting ----
        if (need_cascade) {
            if (fast) {
                unsigned m0 = smask & 0xFu, m1 = (smask >> 4) & 0xFu;
                unsigned packed = ((m0 * 0x00204081u) & 0x01010101u)
                                + ((m1 * 0x00204081u) & 0x01010101u);
                packed += __shfl_xor_sync(0xFFFFFFFFu, packed, 16);
                if ((tid & 31) < 16 && packed)
                    atomicAdd(&cnt[buf][tid & 15], packed);   // byte c&3 of word c>>2
            } else {
                #pragma unroll
                for (int k = 0; k < 8; k++)
                    if (smask & (1u << k)) {
                        int d = h * HALF + 4 * tid + (k & 3) + (k >> 2) * 2048;
                        atomicAdd(&cf_slow[buf][__ldg(&cids[d])], 1.0f);
                    }
            }
        }

        // ---- prefetch next x (hidden behind cascade exchange) ----
        if (need_cascade) {
            const float4* xn = x4 + (size_t)(t + 1) * step4;
            float4 a = __ldg(xn), c = __ldg(xn + 512);
            xv[0]=a.x; xv[1]=a.y; xv[2]=a.z; xv[3]=a.w;
            xv[4]=c.x; xv[5]=c.y; xv[6]=c.z; xv[7]=c.w;
        }

        // ---- reset + streaming stores (independent of cascade result) ----
        {
            float sv[8];
            #pragma unroll
            for (int k = 0; k < 8; k++) {
                float sk = (smask >> k) & 1u ? 1.0f : 0.0f;
                sv[k] = sk;
                v[k] = fmaf(-sk, th[k], v[k]);
            }
            float4* st = s4 + (size_t)t * step4;
            float4* vt = v4 + (size_t)t * step4;
            __stcs(st,       make_float4(sv[0], sv[1], sv[2], sv[3]));
            __stcs(st + 512, make_float4(sv[4], sv[5], sv[6], sv[7]));
            __stcs(vt,       make_float4(v[0], v[1], v[2], v[3]));
            __stcs(vt + 512, make_float4(v[4], v[5], v[6], v[7]));
        }

        if (need_cascade) {
            __syncthreads();   // local counts complete

            // ---- ship local counts to partner CTA (DSMEM) ----
            if (fast) {
                if (tid < 16)
                    st_cluster_u32(mapa_u32(smem_u32(&rcnt[buf][tid]), prank), cnt[buf][tid]);
            } else {
                if (tid < NC)
                    st_cluster_u32(mapa_u32(smem_u32(&rslow[buf][tid]), prank),
                                   __float_as_uint(cf_slow[buf][tid]));
            }
            cluster_sync();    // both directions: remote counts visible

            // ---- phase A: distributed partial dot (512 threads, 2 count-words each) ----
            {
                const int g = tid >> 6, c = tid & 63;
                float acc = 0.0f;
                #pragma unroll
                for (int p = 0; p < 2; p++) {
                    const int w = g + 8 * p;          // count word -> clusters 4w..4w+3
                    float f0, f1, f2, f3;
                    if (fast) {
                        unsigned u = cnt[buf][w] + rcnt[buf][w];   // bytes <=128, no carry
                        f0 = __uint_as_float(__byte_perm(u, 0x4B000000u, 0x7540)) - 8388608.0f;
                        f1 = __uint_as_float(__byte_perm(u, 0x4B000000u, 0x7541)) - 8388608.0f;
                        f2 = __uint_as_float(__byte_perm(u, 0x4B000000u, 0x7542)) - 8388608.0f;
                        f3 = __uint_as_float(__byte_perm(u, 0x4B000000u, 0x7543)) - 8388608.0f;
                    } else {
                        f0 = cf_slow[buf][4 * w + 0] + rslow[buf][4 * w + 0];
                        f1 = cf_slow[buf][4 * w + 1] + rslow[buf][4 * w + 1];
                        f2 = cf_slow[buf][4 * w + 2] + rslow[buf][4 * w + 2];
                        f3 = cf_slow[buf][4 * w + 3] + rslow[buf][4 * w + 3];
                    }
                    const float* wr = &Wts[(4 * w) * NC + c];
                    acc += (f0 * wr[0] + f1 * wr[NC]) + (f2 * wr[2 * NC] + f3 * wr[3 * NC]);
                }
                partial[g][c] = acc;

                if (tid < 16) cnt[buf ^ 1][tid] = 0u;       // consumed two syncs ago
                if (tid < NC) cf_slow[buf ^ 1][tid] = 0.0f;
            }

            __syncthreads();   // partials ready

            // ---- phase B: 64-thread combine ----
            if (tid < NC) {
                float a0 = partial[0][tid] + partial[1][tid];
                float a1 = partial[2][tid] + partial[3][tid];
                float a2 = partial[4][tid] + partial[5][tid];
                float a3 = partial[6][tid] + partial[7][tid];
                ns[tid] = ((a0 + a1) + (a2 + a3)) * g_sm[tid];
            }

            __syncthreads();   // ns ready

            // ---- apply cascade to i_syn ----
            if (fast) {
                float4 nsv = *(const float4*)&ns[4 * (tid & 15)];
                isyn[0] += nsv.x; isyn[1] += nsv.y; isyn[2] += nsv.z; isyn[3] += nsv.w;
                isyn[4] += nsv.x; isyn[5] += nsv.y; isyn[6] += nsv.z; isyn[7] += nsv.w;
            } else {
                #pragma unroll
                for (int k = 0; k < 8; k++) {
                    int d = h * HALF + 4 * tid + (k & 3) + (k >> 2) * 2048;
                    isyn[k] += ns[__ldg(&cids[d])];
                }
            }
        }
    }

    cluster_sync();   // no CTA exits while peer DSMEM traffic could be in flight
}

extern "C" void kernel_launch(void* const* d_in, const int* in_sizes, int n_in,
                              void* d_out, int out_size)
{
    const float* x      = (const float*)d_in[0];   // current_in [T,B,D]
    const float* th_raw = (const float*)d_in[1];   // threshold_raw [D]
    const float* bm_raw = (const float*)d_in[2];   // beta_mem_raw
    const float* bs_raw = (const float*)d_in[3];   // beta_syn_raw
    const float* nw     = (const float*)d_in[4];   // neighbor_weights [NC,NC]
    const float* gain   = (const float*)d_in[5];   // cluster_gain [NC]
    const int*   cids   = (const int*)d_in[6];     // cluster_ids [D]

    float* out_s = (float*)d_out;
    float* out_v = out_s + (size_t)T_STEPS * BATCH * DIM;

    assoc_lif_kernel<<<2 * BATCH, TPB>>>(x, th_raw, bm_raw, bs_raw, nw, gain, cids,
                                         out_s, out_v);
}

// round 13
// speedup vs baseline: 1.3645x; 1.3645x over previous
#include <cuda_runtime.h>
#include <cuda_bf16.h>
#include <math.h>

// AssociativeLIF forward: T=8, B=128, D=8192, NC=64
// d_out = [ ss (T,B,D) | vt (T,B,D) ] float32
// One CTA per batch row. Thread owns d = 4*tid + j (h=0) and d = 4096 + 4*tid + j, j=0..3.
// Fast path (cids[d] == d%64): all 8 neurons of a thread hit clusters 4*(tid&15)+j.
// Cascade dot: thread (c=tid>>4, g=tid&15) -> partial over count-word g, shfl-reduced.

#define T_STEPS 8
#define BATCH   128
#define DIM     8192
#define NC      64
#define TPB     1024
#define V_RESET (-0.1f)

__global__ __launch_bounds__(TPB, 1)
void assoc_lif_kernel(const float* __restrict__ x,        // [T,B,D]
                      const float* __restrict__ th_raw,   // [D]
                      const float* __restrict__ bm_raw,   // [1]
                      const float* __restrict__ bs_raw,   // [1]
                      const float* __restrict__ nw,       // [NC,NC]
                      const float* __restrict__ gain,     // [NC]
                      const int*   __restrict__ cids,     // [D]
                      float* __restrict__ out_s,          // [T,B,D]
                      float* __restrict__ out_v)          // [T,B,D]
{
    // W2[c*64 + j] = sigmoid(nw[c][j]) / 128  (identity layout; /128 exact)
    __shared__ __align__(16) float    W2[NC * NC];
    __shared__ float                  g_sm[NC];
    __shared__ unsigned               cnt[2][16];      // packed byte counts, double-buffered
    __shared__ __align__(16) float    cf_slow[2][NC];  // fallback float counts
    __shared__ __align__(16) float    ns[NC];
    __shared__ float bm_sh, bs_sh;

    const int b   = blockIdx.x;
    const int tid = threadIdx.x;

    // ---- one-time parameter prep ----
    for (int idx = tid; idx < NC * NC; idx += TPB)
        W2[idx] = (1.0f / (1.0f + expf(-nw[idx]))) * (1.0f / 128.0f);
    if (tid < NC)      g_sm[tid] = gain[tid];
    if (tid < 32)      ((unsigned*)cnt)[tid] = 0u;
    if (tid < 2 * NC)  ((float*)cf_slow)[tid] = 0.0f;
    if (tid == 0) {
        float bm = 1.0f / (1.0f + expf(-bm_raw[0]));
        bm_sh = fminf(fmaxf(bm, 0.8f), 0.98f);
        bs_sh = 1.0f / (1.0f + expf(-bs_raw[0]));
    }

    // fast path iff cids[d] == d % 64 for this thread's 8 neurons
    bool okf = true;
    #pragma unroll
    for (int j = 0; j < 4; j++) {
        okf &= (cids[4 * tid + j]        == ((4 * tid + j) & 63));
        okf &= (cids[4 * tid + 4096 + j] == ((4 * tid + j) & 63));
    }
    const bool fast = (__syncthreads_and((int)okf) != 0);   // also fences smem init

    const float bm = bm_sh, bs = bs_sh, om = 1.0f - bm;

    const size_t bd4   = (size_t)b * DIM / 4;
    const size_t step4 = (size_t)BATCH * DIM / 4;

    const float4* x4 = (const float4*)x     + bd4 + tid;
    float4*       s4 = (float4*)out_s       + bd4 + tid;
    float4*       v4 = (float4*)out_v       + bd4 + tid;

    // ---- per-thread state ----
    float v[8], isyn[8], th[8], xv[8];
    unsigned s1 = 0, s2 = 0;            // spike masks at t-1, t-2 (refractory)
    {
        const float4* t4 = (const float4*)th_raw + tid;
        float4 t0 = t4[0], t1 = t4[1024];
        th[0]=t0.x; th[1]=t0.y; th[2]=t0.z; th[3]=t0.w;
        th[4]=t1.x; th[5]=t1.y; th[6]=t1.z; th[7]=t1.w;
        #pragma unroll
        for (int k = 0; k < 8; k++) {
            th[k] = fminf(fmaxf(th[k], 0.05f), 0.5f);
            v[k] = 0.0f; isyn[k] = 0.0f;
        }
        float4 a = x4[0], c = x4[1024];     // preload t=0
        xv[0]=a.x; xv[1]=a.y; xv[2]=a.z; xv[3]=a.w;
        xv[4]=c.x; xv[5]=c.y; xv[6]=c.z; xv[7]=c.w;
    }

    for (int t = 0; t < T_STEPS; t++) {
        const int buf = t & 1;
        const bool need_cascade = (t + 1 < T_STEPS);   // i_syn dead after last step

        // ---- LIF update + spike (refrac>0 <=> spiked at t-1 or t-2) ----
        const unsigned refr = s1 | s2;
        unsigned smask = 0;
        #pragma unroll
        for (int k = 0; k < 8; k++) {
            isyn[k] = fmaf(bs, isyn[k], xv[k]);
            float nv = fmaf(bm, v[k], om * isyn[k]);
            v[k] = ((refr >> k) & 1u) ? V_RESET : nv;
            if (v[k] >= th[k]) smask |= (1u << k);
        }
        s2 = s1; s1 = smask;

        // ---- spike counting (parallel, pre-barrier) ----
        if (need_cascade) {
            if (fast) {
                unsigned m0 = smask & 0xFu, m1 = (smask >> 4) & 0xFu;
                unsigned packed = ((m0 * 0x00204081u) & 0x01010101u)
                                + ((m1 * 0x00204081u) & 0x01010101u);
                packed += __shfl_xor_sync(0xFFFFFFFFu, packed, 16);
                if ((tid & 31) < 16 && packed)
                    atomicAdd(&cnt[buf][tid & 15], packed);   // byte c&3 of word c>>2
            } else {
                #pragma unroll
                for (int k = 0; k < 8; k++)
                    if (smask & (1u << k)) {
                        int d = 4 * tid + (k & 3) + (k >> 2) * 4096;
                        atomicAdd(&cf_slow[buf][__ldg(&cids[d])], 1.0f);   // +1.0: exact, order-free
                    }
            }

            // ---- prefetch next x (hidden behind cascade barriers) ----
            const float4* xn = x4 + (size_t)(t + 1) * step4;
            float4 a = __ldg(xn), c = __ldg(xn + 1024);
            xv[0]=a.x; xv[1]=a.y; xv[2]=a.z; xv[3]=a.w;
            xv[4]=c.x; xv[5]=c.y; xv[6]=c.z; xv[7]=c.w;
        }

        // ---- reset + streaming stores (independent of cascade result) ----
        {
            float sv[8];
            #pragma unroll
            for (int k = 0; k < 8; k++) {
                float sk = (smask >> k) & 1u ? 1.0f : 0.0f;
                sv[k] = sk;
                v[k] = fmaf(-sk, th[k], v[k]);
            }
            float4* st = s4 + (size_t)t * step4;
            float4* vt = v4 + (size_t)t * step4;
            __stcs(st,        make_float4(sv[0], sv[1], sv[2], sv[3]));
            __stcs(st + 1024, make_float4(sv[4], sv[5], sv[6], sv[7]));
            __stcs(vt,        make_float4(v[0], v[1], v[2], v[3]));
            __stcs(vt + 1024, make_float4(v[4], v[5], v[6], v[7]));
        }

        if (!need_cascade) break;      // last step: no cascade consumer

        __syncthreads();   // counts complete

        // ---- fused dot: thread (c=tid>>4, g=tid&15), shfl-reduce over g ----
        {
            const int c = tid >> 4, g = tid & 15;
            float f0, f1, f2, f3;
            if (fast) {
                unsigned u = cnt[buf][g];
                f0 = __uint_as_float(__byte_perm(u, 0x4B000000u, 0x7540)) - 8388608.0f;
                f1 = __uint_as_float(__byte_perm(u, 0x4B000000u, 0x7541)) - 8388608.0f;
                f2 = __uint_as_float(__byte_perm(u, 0x4B000000u, 0x7542)) - 8388608.0f;
                f3 = __uint_as_float(__byte_perm(u, 0x4B000000u, 0x7543)) - 8388608.0f;
            } else {
                float4 cf4 = ((const float4*)cf_slow[buf])[g];
                f0 = cf4.x; f1 = cf4.y; f2 = cf4.z; f3 = cf4.w;
            }
            // W2 row strip for (c, 4g..4g+3): one conflict-free LDS.128
            float4 w = ((const float4*)W2)[tid];
            float acc = (f0 * w.x + f1 * w.y) + (f2 * w.z + f3 * w.w);
            acc += __shfl_xor_sync(0xFFFFFFFFu, acc, 1);
            acc += __shfl_xor_sync(0xFFFFFFFFu, acc, 2);
            acc += __shfl_xor_sync(0xFFFFFFFFu, acc, 4);
            acc += __shfl_xor_sync(0xFFFFFFFFu, acc, 8);
            if (g == 0) ns[c] = acc * g_sm[c];

            if (tid < 16) cnt[buf ^ 1][tid] = 0u;        // consumed two syncs ago
            if (tid < NC) cf_slow[buf ^ 1][tid] = 0.0f;
        }

        __syncthreads();   // ns ready (+ next-buf zeroing ordered before next atomics)

        // ---- apply cascade to i_syn ----
        if (fast) {
            float4 nsv = ((const float4*)ns)[tid & 15];
            isyn[0] += nsv.x; isyn[1] += nsv.y; isyn[2] += nsv.z; isyn[3] += nsv.w;
            isyn[4] += nsv.x; isyn[5] += nsv.y; isyn[6] += nsv.z; isyn[7] += nsv.w;
        } else {
            #pragma unroll
            for (int k = 0; k < 8; k++) {
                int d = 4 * tid + (k & 3) + (k >> 2) * 4096;
                isyn[k] += ns[__ldg(&cids[d])];
            }
        }
    }
}

extern "C" void kernel_launch(void* const* d_in, const int* in_sizes, int n_in,
                              void* d_out, int out_size)
{
    const float* x      = (const float*)d_in[0];   // current_in [T,B,D]
    const float* th_raw = (const float*)d_in[1];   // threshold_raw [D]
    const float* bm_raw = (const float*)d_in[2];   // beta_mem_raw
    const float* bs_raw = (const float*)d_in[3];   // beta_syn_raw
    const float* nw     = (const float*)d_in[4];   // neighbor_weights [NC,NC]
    const float* gain   = (const float*)d_in[5];   // cluster_gain [NC]
    const int*   cids   = (const int*)d_in[6];     // cluster_ids [D]

    float* out_s = (float*)d_out;
    float* out_v = out_s + (size_t)T_STEPS * BATCH * DIM;

    assoc_lif_kernel<<<BATCH, TPB>>>(x, th_raw, bm_raw, bs_raw, nw, gain, cids,
                                     out_s, out_v);
}